// round 17
// baseline (speedup 1.0000x reference)
#include <cuda_runtime.h>

#define NTHREADS 128
#define NBLOCKS 1184  // 148 SMs x 8 blocks (persistent fill)

__constant__ float PSI_C[54];

__global__ void __launch_bounds__(NTHREADS, 8)
transop_expm_kernel(const float* __restrict__ c,
                    const float* __restrict__ x,
                    float* __restrict__ out,
                    int B) {
    const int stride = NBLOCKS * NTHREADS;
    int b = blockIdx.x * NTHREADS + threadIdx.x;
    if (b >= B) return;

    const float2* cp = reinterpret_cast<const float2*>(c) + 3 * b;
    const float*  xp = x + 3 * b;
    float*        op = out + 3 * b;
    const int cstep = 3 * stride;  // float2 units
    const int xstep = 3 * stride;  // float units

    // ---- prologue loads ----
    float2 ca = __ldcs(cp + 0);
    float2 cb = __ldcs(cp + 1);
    float2 cd = __ldcs(cp + 2);
    float px0 = __ldcs(xp + 0);
    float px1 = __ldcs(xp + 1);
    float px2 = __ldcs(xp + 2);

    while (true) {
        // ---- T = sum_m c[m]*psi[m]; psi from __constant__ (uniform-const port,
        //      zero GPRs), c consumed directly from prefetch registers ----
        float T[9];
#pragma unroll
        for (int p = 0; p < 9; p++) {
            float s = ca.x * PSI_C[p];
            s = fmaf(ca.y, PSI_C[9 + p], s);
            s = fmaf(cb.x, PSI_C[18 + p], s);
            s = fmaf(cb.y, PSI_C[27 + p], s);
            s = fmaf(cd.x, PSI_C[36 + p], s);
            s = fmaf(cd.y, PSI_C[45 + p], s);
            T[p] = s;
        }

        int bn = b + stride;
        bool more = bn < B;
        if (more) {
            cp += cstep;
            ca = __ldcs(cp + 0);
            cb = __ldcs(cp + 1);
            cd = __ldcs(cp + 2);
        }
        float x0 = px0, x1 = px1, x2 = px2;
        if (more) {
            xp += xstep;
            px0 = __ldcs(xp + 0);
            px1 = __ldcs(xp + 1);
            px2 = __ldcs(xp + 2);
        }

        // ---- early matvecs on RAW T (parallel ILP branch) ----
        float v0 = fmaf(T[0], x0, fmaf(T[1], x1, T[2] * x2));  // v = T x
        float v1 = fmaf(T[3], x0, fmaf(T[4], x1, T[5] * x2));
        float v2 = fmaf(T[6], x0, fmaf(T[7], x1, T[8] * x2));
        float w0 = fmaf(T[0], v0, fmaf(T[1], v1, T[2] * v2));  // w = T^2 x
        float w1 = fmaf(T[3], v0, fmaf(T[4], v1, T[5] * v2));
        float w2 = fmaf(T[6], v0, fmaf(T[7], v1, T[8] * v2));

        // ---- invariants of T ----
        float mu = (T[0] + T[4] + T[8]) * (1.0f / 3.0f);
        float mu2 = mu * mu;

        float td = T[0] * T[0];
        td = fmaf(T[4], T[4], td);
        td = fmaf(T[8], T[8], td);
        float to = T[1] * T[3];
        to = fmaf(T[2], T[6], to);
        to = fmaf(T[5], T[7], to);
        float pc = fmaf(0.5f, td, to);
        pc = fmaf(-1.5f, mu2, pc);

        float m0 = fmaf(T[4], T[8], -T[5] * T[7]);
        float mA = fmaf(T[0], T[8], -T[2] * T[6]);
        float mB = fmaf(T[0], T[4], -T[1] * T[3]);
        float c2s = m0 + mA + mB;
        float m1 = fmaf(T[5], T[6], -T[3] * T[8]);
        float m2 = fmaf(T[3], T[7], -T[4] * T[6]);
        float det = T[0] * m0;
        det = fmaf(T[1], m1, det);
        det = fmaf(T[2], m2, det);
        float qc = fmaf(2.0f * mu, mu2, fmaf(-c2s, mu, det));

        // ---- Y = T0/4 ----
        float pY = pc * (1.0f / 16.0f);
        float qY = qc * (1.0f / 64.0f);

        // ---- exp(Y) mod (X^3 - pY X - qY), Horner deg-10 ----
        float s0 = 1.0f / 3628800.0f;
        float s1 = 0.0f, s2 = 0.0f;
        const float w9[10] = {1.0f,
                              1.0f,
                              1.0f / 2.0f,
                              1.0f / 6.0f,
                              1.0f / 24.0f,
                              1.0f / 120.0f,
                              1.0f / 720.0f,
                              1.0f / 5040.0f,
                              1.0f / 40320.0f,
                              1.0f / 362880.0f};
#pragma unroll
        for (int k = 9; k >= 0; k--) {
            float n0 = fmaf(s2, qY, w9[k]);
            float n1 = fmaf(s2, pY, s0);
            s2 = s1;
            s0 = n0;
            s1 = n1;
        }

        // ---- 2 squarings in coefficient space ----
#pragma unroll
        for (int i = 0; i < 2; i++) {
            float d0 = s0 + s0;
            float b0 = s0 * s0;
            float b1 = d0 * s1;
            float b2 = fmaf(s1, s1, d0 * s2);
            float b3 = (s1 + s1) * s2;
            float b4 = s2 * s2;
            s0 = fmaf(qY, b3, b0);
            s1 = fmaf(pY, b3, fmaf(qY, b4, b1));
            s2 = fmaf(pY, b4, b2);
        }

        // ---- fold e^mu, scales, traceless shift ----
        float emu = __expf(mu);
        float g0 = s0 * emu;
        float g1 = s1 * emu * 0.25f;
        float g2 = s2 * emu * 0.0625f;
        float h2 = g2;
        float h1 = fmaf(-2.0f * mu, g2, g1);
        float h0 = fmaf(mu2, g2, fmaf(-mu, g1, g0));

        float y0 = fmaf(h0, x0, fmaf(h1, v0, h2 * w0));
        float y1 = fmaf(h0, x1, fmaf(h1, v1, h2 * w1));
        float y2 = fmaf(h0, x2, fmaf(h1, v2, h2 * w2));

        __stcs(op + 0, y0);
        __stcs(op + 1, y1);
        __stcs(op + 2, y2);

        if (!more) break;
        b = bn;
        op += xstep;
    }
}

extern "C" void kernel_launch(void* const* d_in, const int* in_sizes, int n_in,
                              void* d_out, int out_size) {
    // Identify inputs by element count: psi=54, c=B*6, x=B*3
    const float* c = nullptr;
    const float* x = nullptr;
    const float* psi = nullptr;
    long long maxsz = 0;
    for (int i = 0; i < n_in; i++)
        if ((long long)in_sizes[i] > maxsz) maxsz = in_sizes[i];
    int B = (int)(maxsz / 6);
    for (int i = 0; i < n_in; i++) {
        if (in_sizes[i] == 54) psi = (const float*)d_in[i];
        else if (in_sizes[i] == B * 6) c = (const float*)d_in[i];
        else if (in_sizes[i] == B * 3) x = (const float*)d_in[i];
    }

    // Device-to-device async copy into constant bank (graph-capturable).
    cudaMemcpyToSymbolAsync(PSI_C, psi, 54 * sizeof(float), 0,
                            cudaMemcpyDeviceToDevice, 0);

    float* out = (float*)d_out;
    transop_expm_kernel<<<NBLOCKS, NTHREADS>>>(c, x, out, B);
}